// round 2
// baseline (speedup 1.0000x reference)
#include <cuda_runtime.h>
#include <math.h>
#include <stdint.h>

// Problem constants
#define Bn   64
#define Sn   512
#define Dn   256
#define Hn   4
#define HDn  64
#define Tn   24
#define NI   96          // H * T
#define NTOK (Bn * Sn)   // 32768

typedef unsigned long long ull;

// ---------------- scratch (device globals; no allocations allowed) ----------
__device__ __align__(16) float g_qu[Bn * Hn * HDn];   // [b][h][hd]
__device__ __align__(16) float g_qt[Tn * Hn * HDn];   // [t][h][hd]
__device__ __align__(16) float g_k [Hn * Tn * HDn];   // [h][t][hd]
__device__ __align__(16) float g_v [Hn * Tn * HDn];   // [h][t][hd]
__device__ __align__(16) float g_P [Bn * Tn * NI];    // [b][th][h*24+t] = exp(score - rowmax)
__device__ __align__(16) float g_VU[NI * Dn];         // [h*24+t][d]

// ---------------- packed f32x2 helpers ---------------------------------------
__device__ __forceinline__ ull pk2(float x, float y) {
    ull r;
    asm("mov.b64 %0, {%1, %2};" : "=l"(r) : "f"(x), "f"(y));
    return r;
}
__device__ __forceinline__ void fma2(ull& d, ull a, ull b) {
    asm("fma.rn.f32x2 %0, %1, %2, %0;" : "+l"(d) : "l"(a), "l"(b));
}

// ---------------- P1: qu, qt, k, v (one warp per dot-256) ---------------------
// warp regions: [0,16384) qu | [16384,22528) qt | [22528,28672) k | [28672,34816) v
__global__ void precompute_qkv(const float* __restrict__ ts,
                               const int*   __restrict__ user,
                               const float* __restrict__ upref,
                               const float* __restrict__ Wq, const float* __restrict__ bq,
                               const float* __restrict__ Wk, const float* __restrict__ bk,
                               const float* __restrict__ Wv, const float* __restrict__ bv) {
    int w    = (blockIdx.x * blockDim.x + threadIdx.x) >> 5;
    int lane = threadIdx.x & 31;
    if (w >= 34816) return;

    const float* in;
    const float* wt;
    float bias = 0.f;
    float* out;

    if (w < 16384) {                       // qu: w = b*256 + h*64 + hd
        int b  = w >> 8;
        int hh = w & 255;                  // h*64+hd
        in   = upref + (size_t)user[b] * Dn;
        wt   = Wq + (size_t)hh * (2 * Dn);
        bias = bq[hh];
        out  = g_qu + w;
    } else if (w < 22528) {                // qt: r = t*256 + h*64 + hd
        int r  = w - 16384;
        int hh = r & 255;
        in   = ts + (r >> 8) * Dn;
        wt   = Wq + (size_t)hh * (2 * Dn) + Dn;   // second half of Wq row
        out  = g_qt + r;
    } else if (w < 28672) {                // k: r = h*1536 + t*64 + hd
        int r   = w - 22528;
        int h   = r / 1536;
        int rem = r - h * 1536;
        int t   = rem >> 6;
        int hd  = rem & 63;
        in   = ts + t * Dn;
        wt   = Wk + (size_t)(h * HDn + hd) * Dn;
        bias = bk[h * HDn + hd];
        out  = g_k + r;
    } else {                               // v
        int r   = w - 28672;
        int h   = r / 1536;
        int rem = r - h * 1536;
        int t   = rem >> 6;
        int hd  = rem & 63;
        in   = ts + t * Dn;
        wt   = Wv + (size_t)(h * HDn + hd) * Dn;
        bias = bv[h * HDn + hd];
        out  = g_v + r;
    }

    float acc = 0.f;
#pragma unroll
    for (int j = 0; j < 8; j++)
        acc = fmaf(in[lane + 32 * j], wt[lane + 32 * j], acc);
#pragma unroll
    for (int o = 16; o; o >>= 1)
        acc += __shfl_xor_sync(0xFFFFFFFFu, acc, o);
    if (lane == 0) *out = acc + bias;
}

// ---------------- P2 (merged): blocks [0,768)  -> P table
//                               blocks [768,864) -> VU table -----------------
// P: one warp per (b, th, h); lane t < 24 does a dot-64.
// VU[i][d] = Wu[d, h*64 : h*64+64] . v[h][t][:]
__global__ void precompute_P_VU(const float* __restrict__ Wu) {
    if (blockIdx.x < 768) {
        int w    = (blockIdx.x * blockDim.x + threadIdx.x) >> 5;  // (b*24+th)*4 + h
        int lane = threadIdx.x & 31;
        int h   = w & 3;
        int bth = w >> 2;                 // b*24 + th
        int th  = bth % Tn;
        int b   = bth / Tn;

        float s = -INFINITY;
        if (lane < Tn) {
            const float* qa = g_qu + (b * Hn + h) * HDn;
            const float* qb = g_qt + (th * Hn + h) * HDn;
            const float* kk = g_k + (h * Tn + lane) * HDn;
            float acc = 0.f;
#pragma unroll 8
            for (int j = 0; j < HDn; j++)
                acc = fmaf(qa[j] + qb[j], kk[j], acc);
            s = acc * 0.125f;             // 1/sqrt(HD) = 1/8
        }
        float m = s;
#pragma unroll
        for (int o = 16; o; o >>= 1)
            m = fmaxf(m, __shfl_xor_sync(0xFFFFFFFFu, m, o));
        if (lane < Tn)
            g_P[bth * NI + h * Tn + lane] = expf(s - m);
    } else {
        int i = blockIdx.x - 768;         // h*24 + t
        int d = threadIdx.x;              // 0..255
        int h = i / Tn;
        const float* vr = g_v + i * HDn;
        const float* wr = Wu + (size_t)d * Dn + h * HDn;
        float acc = 0.f;
#pragma unroll 8
        for (int j = 0; j < HDn; j++)
            acc = fmaf(wr[j], vr[j], acc);
        g_VU[i * Dn + d] = acc;
    }
}

// ---------------- main: per-token masked softmax + [64,96]x[96,256] GEMM ------
// grid (S/64, B), 256 threads. Block = 64 tokens of batch row b.
// att2[tok][i] holds the attention weight DUPLICATED as an f32x2 pair so the
// epilogue FFMA2 loop needs zero packing MOVs (LDS.64 feeds fma.rn.f32x2 directly).
__global__ void __launch_bounds__(256, 2)
attn_out_kernel(const int* __restrict__ hour,
                const int* __restrict__ hmask,
                const float* __restrict__ bu,
                float* __restrict__ out) {
    __shared__ ull att2[64 * NI];            // 48 KB exactly (static limit)

    int b   = blockIdx.y;
    int s0  = blockIdx.x * 64;
    int tid = threadIdx.x;
    int warp = tid >> 5, lane = tid & 31;

    // ---- phase B: masked softmax weights (warp per token, 8 tokens/warp) ----
    int nbase = b * Sn + s0 + warp * 8;
    int th[8];
#pragma unroll
    for (int r = 0; r < 8; r++)
        th[r] = hour[nbase + r];             // independent LDGs, MLP=8
#pragma unroll
    for (int r = 0; r < 8; r++) {
        int n = nbase + r;
        bool keep = false;
        if (lane < Tn) keep = (hmask[n * Tn + lane] == 0);   // mask==1 -> excluded
        const float* Pr = g_P + ((size_t)b * Tn + th[r]) * NI;
        float w0 = 0.f, w1 = 0.f, w2 = 0.f, w3 = 0.f;
        if (keep) {
            w0 = Pr[lane];
            w1 = Pr[Tn + lane];
            w2 = Pr[2 * Tn + lane];
            w3 = Pr[3 * Tn + lane];
        }
        float z0 = w0, z1 = w1, z2 = w2, z3 = w3;
#pragma unroll
        for (int o = 16; o; o >>= 1) {
            z0 += __shfl_xor_sync(0xFFFFFFFFu, z0, o);
            z1 += __shfl_xor_sync(0xFFFFFFFFu, z1, o);
            z2 += __shfl_xor_sync(0xFFFFFFFFu, z2, o);
            z3 += __shfl_xor_sync(0xFFFFFFFFu, z3, o);
        }
        if (lane < Tn) {
            int tok = warp * 8 + r;
            float a0 = __fdividef(w0, z0);
            float a1 = __fdividef(w1, z1);
            float a2 = __fdividef(w2, z2);
            float a3 = __fdividef(w3, z3);
            att2[tok * NI + lane]          = pk2(a0, a0);
            att2[tok * NI + Tn + lane]     = pk2(a1, a1);
            att2[tok * NI + 2 * Tn + lane] = pk2(a2, a2);
            att2[tok * NI + 3 * Tn + lane] = pk2(a3, a3);
        }
    }
    __syncthreads();

    // ---- phase C: out[64,256] = attn[64,96] @ VU[96,256] + bu ---------------
    // thread: 4 tokens x 16 dims; 32 packed f32x2 accumulators.
    int dg = tid & 15;                 // 16 dim-groups of 16 dims
    int tg = tid >> 4;                 // 16 token-groups of 4 tokens
    int d0 = dg * 16;
    int t0 = tg * 4;

    ull acc[4][8];
    {
        const ulonglong2* bp = reinterpret_cast<const ulonglong2*>(bu + d0);
        ulonglong2 b0 = bp[0], b1 = bp[1], b2 = bp[2], b3 = bp[3];
#pragma unroll
        for (int k = 0; k < 4; k++) {
            acc[k][0] = b0.x; acc[k][1] = b0.y;
            acc[k][2] = b1.x; acc[k][3] = b1.y;
            acc[k][4] = b2.x; acc[k][5] = b2.y;
            acc[k][6] = b3.x; acc[k][7] = b3.y;
        }
    }

    const ull* arow0 = att2 + (t0 + 0) * NI;
    const ull* arow1 = att2 + (t0 + 1) * NI;
    const ull* arow2 = att2 + (t0 + 2) * NI;
    const ull* arow3 = att2 + (t0 + 3) * NI;

#pragma unroll 4
    for (int i = 0; i < NI; i++) {
        const ulonglong2* vp = reinterpret_cast<const ulonglong2*>(g_VU + i * Dn + d0);
        ulonglong2 u0 = vp[0], u1 = vp[1], u2 = vp[2], u3 = vp[3];
        ull v[8] = {u0.x, u0.y, u1.x, u1.y, u2.x, u2.y, u3.x, u3.y};
        ull a0 = arow0[i], a1 = arow1[i], a2 = arow2[i], a3 = arow3[i];
#pragma unroll
        for (int j = 0; j < 8; j++) {
            fma2(acc[0][j], a0, v[j]);
            fma2(acc[1][j], a1, v[j]);
            fma2(acc[2][j], a2, v[j]);
            fma2(acc[3][j], a3, v[j]);
        }
    }

#pragma unroll
    for (int k = 0; k < 4; k++) {
        size_t n = (size_t)(b * Sn + s0 + t0 + k);
        ulonglong2* op = reinterpret_cast<ulonglong2*>(out + n * Dn + d0);
        op[0] = make_ulonglong2(acc[k][0], acc[k][1]);
        op[1] = make_ulonglong2(acc[k][2], acc[k][3]);
        op[2] = make_ulonglong2(acc[k][4], acc[k][5]);
        op[3] = make_ulonglong2(acc[k][6], acc[k][7]);
    }
}

// ---------------- launch ------------------------------------------------------
extern "C" void kernel_launch(void* const* d_in, const int* in_sizes, int n_in,
                              void* d_out, int out_size) {
    const float* ts    = (const float*)d_in[0];
    const int*   user  = (const int*)  d_in[1];
    const int*   hour  = (const int*)  d_in[2];
    const int*   hmask = (const int*)  d_in[3];
    const float* upref = (const float*)d_in[4];
    const float* Wq    = (const float*)d_in[5];
    const float* bq    = (const float*)d_in[6];
    const float* Wk    = (const float*)d_in[7];
    const float* bk    = (const float*)d_in[8];
    const float* Wv    = (const float*)d_in[9];
    const float* bv    = (const float*)d_in[10];
    const float* Wu    = (const float*)d_in[11];
    const float* bu    = (const float*)d_in[12];
    float* out = (float*)d_out;

    // 34816 warps -> 4352 blocks of 256 threads
    precompute_qkv<<<4352, 256>>>(ts, user, upref, Wq, bq, Wk, bk, Wv, bv);
    // blocks [0,768): P table (6144 warps); blocks [768,864): VU table
    precompute_P_VU<<<864, 256>>>(Wu);
    dim3 grid(Sn / 64, Bn);
    attn_out_kernel<<<grid, 256>>>(hour, hmask, bu, out);
}

// round 8
// speedup vs baseline: 1.8950x; 1.8950x over previous
#include <cuda_runtime.h>
#include <math.h>
#include <stdint.h>

// Problem constants
#define Bn   64
#define Sn   512
#define Dn   256
#define Hn   4
#define HDn  64
#define Tn   24
#define NI   96          // H * T
#define NTOK (Bn * Sn)   // 32768

typedef unsigned long long ull;

// ---------------- scratch (device globals; no allocations allowed) ----------
__device__ __align__(16) float g_qu[Bn * Hn * HDn];   // [b][h][hd]
__device__ __align__(16) float g_qt[Tn * Hn * HDn];   // [t][h][hd]
__device__ __align__(16) float g_k [Hn * Tn * HDn];   // [h][t][hd]
__device__ __align__(16) float g_v [Hn * Tn * HDn];   // [h][t][hd]
__device__ __align__(16) float g_P [Bn * Tn * NI];    // [b][th][h*24+t] = exp(score - rowmax)
__device__ __align__(16) float g_VU[NI * Dn];         // [h*24+t][d]

// ---------------- packed f32x2 helpers ---------------------------------------
__device__ __forceinline__ ull pk2(float x, float y) {
    ull r;
    asm("mov.b64 %0, {%1, %2};" : "=l"(r) : "f"(x), "f"(y));
    return r;
}
__device__ __forceinline__ void fma2(ull& d, ull a, ull b) {
    asm("fma.rn.f32x2 %0, %1, %2, %0;" : "+l"(d) : "l"(a), "l"(b));
}

// ---------------- P1: qu, qt, k, v (one warp per dot-256) ---------------------
// warp regions: [0,16384) qu | [16384,22528) qt | [22528,28672) k | [28672,34816) v
// Each lane owns a contiguous 32B (8 floats) of both operands: 2 float4 LDG.128
// per operand, 4 independent loads in flight, 8 FFMA, then a 5-step shuffle tree.
__global__ void precompute_qkv(const float* __restrict__ ts,
                               const int*   __restrict__ user,
                               const float* __restrict__ upref,
                               const float* __restrict__ Wq, const float* __restrict__ bq,
                               const float* __restrict__ Wk, const float* __restrict__ bk,
                               const float* __restrict__ Wv, const float* __restrict__ bv) {
    int w    = (blockIdx.x * blockDim.x + threadIdx.x) >> 5;
    int lane = threadIdx.x & 31;
    if (w >= 34816) return;

    const float* in;
    const float* wt;
    float bias = 0.f;
    float* out;

    if (w < 16384) {                       // qu: w = b*256 + h*64 + hd
        int b  = w >> 8;
        int hh = w & 255;                  // h*64+hd
        in   = upref + (size_t)user[b] * Dn;
        wt   = Wq + (size_t)hh * (2 * Dn);
        bias = bq[hh];
        out  = g_qu + w;
    } else if (w < 22528) {                // qt: r = t*256 + h*64 + hd
        int r  = w - 16384;
        int hh = r & 255;
        in   = ts + (r >> 8) * Dn;
        wt   = Wq + (size_t)hh * (2 * Dn) + Dn;   // second half of Wq row
        out  = g_qt + r;
    } else if (w < 28672) {                // k: r = h*1536 + t*64 + hd
        int r   = w - 22528;
        int h   = r / 1536;
        int rem = r - h * 1536;
        int t   = rem >> 6;
        int hd  = rem & 63;
        in   = ts + t * Dn;
        wt   = Wk + (size_t)(h * HDn + hd) * Dn;
        bias = bk[h * HDn + hd];
        out  = g_k + r;
    } else {                               // v
        int r   = w - 28672;
        int h   = r / 1536;
        int rem = r - h * 1536;
        int t   = rem >> 6;
        int hd  = rem & 63;
        in   = ts + t * Dn;
        wt   = Wv + (size_t)(h * HDn + hd) * Dn;
        bias = bv[h * HDn + hd];
        out  = g_v + r;
    }

    // all operand bases are 256-float-row aligned -> 16B-aligned float4 access
    const float4* in4 = reinterpret_cast<const float4*>(in) + lane * 2;
    const float4* wt4 = reinterpret_cast<const float4*>(wt) + lane * 2;
    float4 a0 = in4[0], a1 = in4[1];
    float4 b0 = wt4[0], b1 = wt4[1];

    float acc = 0.f;
    acc = fmaf(a0.x, b0.x, acc); acc = fmaf(a0.y, b0.y, acc);
    acc = fmaf(a0.z, b0.z, acc); acc = fmaf(a0.w, b0.w, acc);
    acc = fmaf(a1.x, b1.x, acc); acc = fmaf(a1.y, b1.y, acc);
    acc = fmaf(a1.z, b1.z, acc); acc = fmaf(a1.w, b1.w, acc);
#pragma unroll
    for (int o = 16; o; o >>= 1)
        acc += __shfl_xor_sync(0xFFFFFFFFu, acc, o);
    if (lane == 0) *out = acc + bias;
}

// ---------------- P2 (merged): blocks [0,768)  -> P table
//                               blocks [768,864) -> VU table -----------------
__global__ void precompute_P_VU(const float* __restrict__ Wu) {
    if (blockIdx.x < 768) {
        int w    = (blockIdx.x * blockDim.x + threadIdx.x) >> 5;  // (b*24+th)*4 + h
        int lane = threadIdx.x & 31;
        int h   = w & 3;
        int bth = w >> 2;                 // b*24 + th
        int th  = bth % Tn;
        int b   = bth / Tn;

        float s = -INFINITY;
        if (lane < Tn) {
            const float* qa = g_qu + (b * Hn + h) * HDn;
            const float* qb = g_qt + (th * Hn + h) * HDn;
            const float* kk = g_k + (h * Tn + lane) * HDn;
            float acc = 0.f;
#pragma unroll 8
            for (int j = 0; j < HDn; j++)
                acc = fmaf(qa[j] + qb[j], kk[j], acc);
            s = acc * 0.125f;             // 1/sqrt(HD) = 1/8
        }
        float m = s;
#pragma unroll
        for (int o = 16; o; o >>= 1)
            m = fmaxf(m, __shfl_xor_sync(0xFFFFFFFFu, m, o));
        if (lane < Tn)
            g_P[bth * NI + h * Tn + lane] = expf(s - m);
    } else {
        int i = blockIdx.x - 768;         // h*24 + t
        int d = threadIdx.x;              // 0..255
        int h = i / Tn;
        const float* vr = g_v + i * HDn;
        const float* wr = Wu + (size_t)d * Dn + h * HDn;
        float acc = 0.f;
#pragma unroll 8
        for (int j = 0; j < HDn; j++)
            acc = fmaf(wr[j], vr[j], acc);
        g_VU[i * Dn + d] = acc;
    }
}

// ---------------- main: per-token masked softmax + [32,96]x[96,256] GEMM ------
// grid (S/32, B), 256 threads (8 warps). Block = 32 tokens of batch row b.
// att2[tok][i] holds the attention weight DUPLICATED as an f32x2 pair.
// Phase C mapping (spill-free, warp-coalesced):
//   warp w: token group tg = w>>1 (8 tokens), dim half dh = w&1 (128 dims)
//   lane l: 4 dims at d0 = dh*128 + l*4  -> each warp LDG.128 covers a
//   contiguous 512B of a VU row (4 fully-used L1 lines).
// Thread tile: 8 tokens x 4 dims -> acc[8][2] f32x2 = 32 regs. No spills.
__global__ void __launch_bounds__(256, 2)
attn_out_kernel(const int* __restrict__ hour,
                const int* __restrict__ hmask,
                const float* __restrict__ bu,
                float* __restrict__ out) {
    __shared__ ull att2[32 * NI];            // 24 KB

    int b    = blockIdx.y;
    int s0   = blockIdx.x * 32;
    int tid  = threadIdx.x;
    int warp = tid >> 5, lane = tid & 31;

    // ---- phase B: masked softmax weights (warp per 4 tokens) ----------------
    int nbase = b * Sn + s0 + warp * 4;
    int th[4];
#pragma unroll
    for (int r = 0; r < 4; r++)
        th[r] = hour[nbase + r];             // independent LDGs
#pragma unroll
    for (int r = 0; r < 4; r++) {
        int n = nbase + r;
        bool keep = false;
        if (lane < Tn) keep = (hmask[n * Tn + lane] == 0);   // mask==1 -> excluded
        const float* Pr = g_P + ((size_t)b * Tn + th[r]) * NI;
        float w0 = 0.f, w1 = 0.f, w2 = 0.f, w3 = 0.f;
        if (keep) {
            w0 = Pr[lane];
            w1 = Pr[Tn + lane];
            w2 = Pr[2 * Tn + lane];
            w3 = Pr[3 * Tn + lane];
        }
        float z0 = w0, z1 = w1, z2 = w2, z3 = w3;
#pragma unroll
        for (int o = 16; o; o >>= 1) {
            z0 += __shfl_xor_sync(0xFFFFFFFFu, z0, o);
            z1 += __shfl_xor_sync(0xFFFFFFFFu, z1, o);
            z2 += __shfl_xor_sync(0xFFFFFFFFu, z2, o);
            z3 += __shfl_xor_sync(0xFFFFFFFFu, z3, o);
        }
        if (lane < Tn) {
            int tok = warp * 4 + r;
            float a0 = __fdividef(w0, z0);
            float a1 = __fdividef(w1, z1);
            float a2 = __fdividef(w2, z2);
            float a3 = __fdividef(w3, z3);
            att2[tok * NI + lane]          = pk2(a0, a0);
            att2[tok * NI + Tn + lane]     = pk2(a1, a1);
            att2[tok * NI + 2 * Tn + lane] = pk2(a2, a2);
            att2[tok * NI + 3 * Tn + lane] = pk2(a3, a3);
        }
    }
    __syncthreads();

    // ---- phase C: out[32,256] = attn[32,96] @ VU[96,256] + bu ---------------
    int dh = warp & 1;                   // dim half (128 dims)
    int tg = warp >> 1;                  // token group (8 tokens)
    int d0 = dh * 128 + lane * 4;        // 4 dims per thread
    const ull* arow = att2 + tg * 8 * NI;

    ull acc[8][2];
    {
        float4 b4 = *reinterpret_cast<const float4*>(bu + d0);
        ull b01 = pk2(b4.x, b4.y);
        ull b23 = pk2(b4.z, b4.w);
#pragma unroll
        for (int t = 0; t < 8; t++) { acc[t][0] = b01; acc[t][1] = b23; }
    }

    const float* vu_base = g_VU + d0;
#pragma unroll 2
    for (int i = 0; i < NI; i += 2) {
        // two consecutive VU rows, 16B each (warp covers a contiguous 512B)
        ulonglong2 vu0 = *reinterpret_cast<const ulonglong2*>(vu_base + i * Dn);
        ulonglong2 vu1 = *reinterpret_cast<const ulonglong2*>(vu_base + (i + 1) * Dn);
#pragma unroll
        for (int t = 0; t < 8; t++) {
            // a.x = dup(attn[t][i]), a.y = dup(attn[t][i+1])  (one LDS.128)
            ulonglong2 a = *reinterpret_cast<const ulonglong2*>(arow + t * NI + i);
            fma2(acc[t][0], a.x, vu0.x);
            fma2(acc[t][1], a.x, vu0.y);
            fma2(acc[t][0], a.y, vu1.x);
            fma2(acc[t][1], a.y, vu1.y);
        }
    }

#pragma unroll
    for (int t = 0; t < 8; t++) {
        size_t n = (size_t)(b * Sn + s0 + tg * 8 + t);
        *reinterpret_cast<ulonglong2*>(out + n * Dn + d0) =
            make_ulonglong2(acc[t][0], acc[t][1]);
    }
}

// ---------------- launch ------------------------------------------------------
extern "C" void kernel_launch(void* const* d_in, const int* in_sizes, int n_in,
                              void* d_out, int out_size) {
    const float* ts    = (const float*)d_in[0];
    const int*   user  = (const int*)  d_in[1];
    const int*   hour  = (const int*)  d_in[2];
    const int*   hmask = (const int*)  d_in[3];
    const float* upref = (const float*)d_in[4];
    const float* Wq    = (const float*)d_in[5];
    const float* bq    = (const float*)d_in[6];
    const float* Wk    = (const float*)d_in[7];
    const float* bk    = (const float*)d_in[8];
    const float* Wv    = (const float*)d_in[9];
    const float* bv    = (const float*)d_in[10];
    const float* Wu    = (const float*)d_in[11];
    const float* bu    = (const float*)d_in[12];
    float* out = (float*)d_out;

    // 34816 warps -> 4352 blocks of 256 threads
    precompute_qkv<<<4352, 256>>>(ts, user, upref, Wq, bq, Wk, bk, Wv, bv);
    // blocks [0,768): P table (6144 warps); blocks [768,864): VU table
    precompute_P_VU<<<864, 256>>>(Wu);
    dim3 grid(Sn / 32, Bn);
    attn_out_kernel<<<grid, 256>>>(hour, hmask, bu, out);
}